// round 5
// baseline (speedup 1.0000x reference)
#include <cuda_runtime.h>
#include <cuda_bf16.h>
#include <cooperative_groups.h>
#include <cooperative_groups/reduce.h>

namespace cg = cooperative_groups;

// DimMasking R4: incremental multiplicative softmax.
//  - p <- p * (1-y)^{1/T} via degree-4 poly (y<=0.02), exact MUFU fallback (rare)
//  - packed f32x2 (FFMA2) math throughout
//  - hardware warp reduction (REDUX.F32 via cg::reduce) replaces 5-shfl chain
//  - next-iteration sum fused into the update loop
//  - slow-path trigger tested on packed bits (ALU pipe, no unpack movs)
//  - launch_bounds(256,5) for 62.5% occupancy

#define DD       640
#define HID      64
#define N_ITER   64
#define INV_T    (1.0f / 0.07f)
#define LOG2E    1.4426950408889634f
#define RPC      8
#define NP       10              // pairs per lane (640/32/2)
#define TBITS    0xBCA3D70Au     // bits of -0.02f (threshold on z = -y)

typedef unsigned long long u64;

__device__ __forceinline__ u64 fma2(u64 a, u64 b, u64 c) {
    u64 d; asm("fma.rn.f32x2 %0, %1, %2, %3;" : "=l"(d) : "l"(a), "l"(b), "l"(c)); return d;
}
__device__ __forceinline__ u64 mul2(u64 a, u64 b) {
    u64 d; asm("mul.rn.f32x2 %0, %1, %2;" : "=l"(d) : "l"(a), "l"(b)); return d;
}
__device__ __forceinline__ u64 add2(u64 a, u64 b) {
    u64 d; asm("add.rn.f32x2 %0, %1, %2;" : "=l"(d) : "l"(a), "l"(b)); return d;
}
__device__ __forceinline__ u64 pack2(float x, float y) {
    u64 r; asm("mov.b64 %0, {%1, %2};" : "=l"(r) : "f"(x), "f"(y)); return r;
}
__device__ __forceinline__ float2 unpack2(u64 v) {
    float2 f; asm("mov.b64 {%0, %1}, %2;" : "=f"(f.x), "=f"(f.y) : "l"(v)); return f;
}
__device__ __forceinline__ float ex2f(float x) {
    float r; asm("ex2.approx.ftz.f32 %0, %1;" : "=f"(r) : "f"(x)); return r;
}
__device__ __forceinline__ float lg2f(float x) {
    float r; asm("lg2.approx.ftz.f32 %0, %1;" : "=f"(r) : "f"(x)); return r;
}
__device__ __forceinline__ float rcpf(float x) {
    float r; asm("rcp.approx.ftz.f32 %0, %1;" : "=f"(r) : "f"(x)); return r;
}

__global__ __launch_bounds__(RPC * 32, 5)
void dim_masking_kernel(const float* __restrict__ x,
                        const float* __restrict__ W1,
                        const float* __restrict__ b1,
                        const float* __restrict__ W2,
                        const float* __restrict__ b2,
                        float* __restrict__ out)
{
    __shared__ float2 xs2[RPC][DD / 2];
    __shared__ float2 hs2[RPC][HID / 2];

    cg::thread_block blk = cg::this_thread_block();
    cg::thread_block_tile<32> warp = cg::tiled_partition<32>(blk);

    const int w    = threadIdx.x >> 5;
    const int lane = threadIdx.x & 31;
    const int row  = blockIdx.x * RPC + w;

    const u64* xr = (const u64*)(x + (size_t)row * DD);

    // ---- stage x row into smem as pairs (coalesced) ----
    #pragma unroll
    for (int j = 0; j < NP; j++)
        *(u64*)&xs2[w][lane + 32 * j] = xr[lane + 32 * j];
    __syncwarp();

    const float* xsf = (const float*)xs2[w];

    // ---- GEMM1: hidden units (2*lane, 2*lane+1), packed FMA ----
    u64 acc1 = *(const u64*)&b1[2 * lane];
    #pragma unroll 8
    for (int d = 0; d < DD; d++) {
        float xd = xsf[d];
        acc1 = fma2(pack2(xd, xd), *(const u64*)&W1[d * HID + 2 * lane], acc1);
    }
    {
        float2 a = unpack2(acc1);
        hs2[w][lane] = make_float2(fmaxf(a.x, 0.0f), fmaxf(a.y, 0.0f));
    }
    __syncwarp();

    const float* hsf = (const float*)hs2[w];

    // ---- GEMM2: h pairs at dims 2*lane + 64*j ----
    u64 h2[NP];
    #pragma unroll
    for (int j = 0; j < NP; j++)
        h2[j] = *(const u64*)&b2[2 * lane + 64 * j];
    #pragma unroll 4
    for (int c = 0; c < HID; c++) {
        float hc = hsf[c];
        u64 hv = pack2(hc, hc);
        const float* w2r = &W2[c * DD + 2 * lane];
        #pragma unroll
        for (int j = 0; j < NP; j++)
            h2[j] = fma2(hv, *(const u64*)&w2r[64 * j], h2[j]);
    }

    // ---- init: p = exp2(l - max l); m = 1; running packed sum sacc ----
    float lx[NP], ly[NP];
    float M0 = -3.402823e38f;
    #pragma unroll
    for (int j = 0; j < NP; j++) {
        float2 hf = unpack2(h2[j]);
        lx[j] = -hf.x * (INV_T * LOG2E);
        ly[j] = -hf.y * (INV_T * LOG2E);
        M0 = fmaxf(M0, fmaxf(lx[j], ly[j]));
    }
    M0 = cg::reduce(warp, M0, cg::greater<float>());

    u64 p[NP], m[NP];
    const u64 ONE2 = pack2(1.0f, 1.0f);
    u64 sacc = 0;
    #pragma unroll
    for (int j = 0; j < NP; j++) {
        p[j] = pack2(ex2f(lx[j] - M0), ex2f(ly[j] - M0));
        m[j] = ONE2;
        sacc = (j == 0) ? p[0] : add2(sacc, p[j]);
    }

    const u64 K1 = pack2(14.285714285714286f, 14.285714285714286f);
    const u64 K2 = pack2(94.89795918367347f,  94.89795918367347f);
    const u64 K3 = pack2(388.6297376093295f,  388.6297376093295f);
    const u64 K4 = pack2(1096.491194f,        1096.491194f);

    // ---- 64-iteration incremental recurrence ----
    #pragma unroll 1
    for (int it = 0; it < N_ITER; it++) {
        float2 sf = unpack2(sacc);
        float S = sf.x + sf.y;
        S = cg::reduce(warp, S, cg::plus<float>());   // REDUX.F32 on sm_10x
        float nrS = -rcpf(S);
        u64 nrS2 = pack2(nrS, nrS);

        u64 sn = 0;
        #pragma unroll
        for (int j = 0; j < NP; j++) {
            u64 z = mul2(p[j], nrS2);            // z = -y, y = p/S >= 0
            u64 t = fma2(z, K4, K3);
            t = fma2(z, t, K2);
            t = fma2(z, t, K1);
            u64 f = fma2(z, t, ONE2);            // (1+z)^{1/T} poly, |z|<=0.02
            unsigned zh = (unsigned)(z >> 32);
            unsigned zl = (unsigned)z;
            if (zh > TBITS || zl > TBITS) {      // rare exact path (|z|>0.02)
                float2 zf = unpack2(z);
                float2 ff = unpack2(f);
                if (zl > TBITS)
                    ff.x = ex2f(lg2f(fmaxf(1.0f + zf.x, 0.0f)) * INV_T);
                if (zh > TBITS)
                    ff.y = ex2f(lg2f(fmaxf(1.0f + zf.y, 0.0f)) * INV_T);
                f = pack2(ff.x, ff.y);
            }
            p[j] = mul2(p[j], f);
            m[j] = fma2(z, m[j], m[j]);          // m *= (1 - y)
            sn = (j == 0) ? p[0] : add2(sn, p[j]);
        }
        sacc = sn;
    }

    // ---- out = m * x ----
    u64* orow = (u64*)(out + (size_t)row * DD);
    #pragma unroll
    for (int j = 0; j < NP; j++) {
        u64 xv = *(const u64*)&xs2[w][lane + 32 * j];
        orow[lane + 32 * j] = mul2(m[j], xv);
    }
}

extern "C" void kernel_launch(void* const* d_in, const int* in_sizes, int n_in,
                              void* d_out, int out_size)
{
    const float* x  = (const float*)d_in[0];   // (8192, 640)
    const float* W1 = (const float*)d_in[1];   // (640, 64)
    const float* b1 = (const float*)d_in[2];   // (64,)
    const float* W2 = (const float*)d_in[3];   // (64, 640)
    const float* b2 = (const float*)d_in[4];   // (640,)
    float* out = (float*)d_out;

    const int B = in_sizes[0] / DD;            // 8192
    dim_masking_kernel<<<B / RPC, RPC * 32>>>(x, W1, b1, W2, b2, out);
}